// round 12
// baseline (speedup 1.0000x reference)
#include <cuda_runtime.h>
#include <cuda_bf16.h>
#include <mma.h>
#include <math.h>
#include <stdint.h>

using namespace nvcuda;

#define BB 16
#define SS 1024
#define DD 1024
#define EE 8
#define IM 2048
#define KCAP 256
#define UNCOND_LABEL 1000LL
#define NTOK (BB*SS)
#define NROUT (BB*EE*KCAP)

typedef __nv_bfloat16 bf16;

#define GU_SMEM (1024 + 38912)
#define DN_SMEM (1024 + 37888)

// ---------------- scratch (269MB — proven loadable) ----------------
__device__ float g_cn[EE*DD];
__device__ float g_cos[BB*EE*SS];
__device__ float g_gate[NROUT];
__device__ int   g_tok[NROUT];
__device__ float g_H[(size_t)NROUT * IM];   // fp32; dense phases use rows 0..16383

// ---------------- split helper ----------------
__device__ __forceinline__ void split4(float4 v, uint2& hp, uint2& lp) {
    float vv[4] = {v.x, v.y, v.z, v.w};
    __align__(8) bf16 h[4];
    __align__(8) bf16 l[4];
    #pragma unroll
    for (int j = 0; j < 4; j++) {
        h[j] = __float2bfloat16_rn(vv[j]);
        l[j] = __float2bfloat16_rn(vv[j] - __bfloat162float(h[j]));
    }
    hp = *(uint2*)h; lp = *(uint2*)l;
}

// ---------------- router (proven correct) ----------------
__global__ void k_norm_centers(const float* __restrict__ c) {
    int e = blockIdx.x, tid = threadIdx.x;
    float ss = 0.f;
    for (int j = tid; j < DD; j += 256) { float v = c[e*DD+j]; ss += v*v; }
    #pragma unroll
    for (int o = 16; o > 0; o >>= 1) ss += __shfl_down_sync(0xffffffffu, ss, o);
    __shared__ float red[8];
    if ((tid & 31) == 0) red[tid>>5] = ss;
    __syncthreads();
    if (tid == 0) { float t = 0.f; for (int w = 0; w < 8; w++) t += red[w]; red[0] = t; }
    __syncthreads();
    float inv = 1.f / fmaxf(sqrtf(red[0]), 1e-12f);
    for (int j = tid; j < DD; j += 256) g_cn[e*DD+j] = c[e*DD+j] * inv;
}

__global__ void k_router(const float* __restrict__ hidden) {
    int t = blockIdx.x, b = t >> 10, s = t & 1023, tid = threadIdx.x;
    const float* x = hidden + (size_t)t * DD;
    float acc[9];
    #pragma unroll
    for (int i = 0; i < 9; i++) acc[i] = 0.f;
    for (int j = tid; j < DD; j += 256) {
        float xv = x[j];
        acc[8] = fmaf(xv, xv, acc[8]);
        #pragma unroll
        for (int e = 0; e < EE; e++) acc[e] = fmaf(xv, g_cn[e*DD+j], acc[e]);
    }
    #pragma unroll
    for (int o = 16; o > 0; o >>= 1) {
        #pragma unroll
        for (int i = 0; i < 9; i++) acc[i] += __shfl_down_sync(0xffffffffu, acc[i], o);
    }
    __shared__ float sr[72];
    int lane = tid & 31, wd = tid >> 5;
    if (lane == 0) {
        #pragma unroll
        for (int i = 0; i < 9; i++) sr[i*8+wd] = acc[i];
    }
    __syncthreads();
    if (tid < EE) {
        float nrm = 0.f;
        for (int w = 0; w < 8; w++) nrm += sr[64+w];
        nrm = fmaxf(sqrtf(nrm), 1e-12f);
        float d = 0.f;
        for (int w = 0; w < 8; w++) d += sr[tid*8+w];
        g_cos[((size_t)b*EE+tid)*SS + s] = d / nrm;
    }
}

__global__ void k_softmax_topk() {
    int r = blockIdx.x, tid = threadIdx.x;
    __shared__ float v[SS]; __shared__ int ix[SS]; __shared__ float red[16];
    const float* row = g_cos + (size_t)r * SS;
    float lmax = -1e30f;
    for (int i = tid; i < SS; i += 512) { float t = row[i]; v[i] = t; ix[i] = i; lmax = fmaxf(lmax, t); }
    #pragma unroll
    for (int o = 16; o > 0; o >>= 1) lmax = fmaxf(lmax, __shfl_down_sync(0xffffffffu, lmax, o));
    if ((tid & 31) == 0) red[tid>>5] = lmax;
    __syncthreads();
    if (tid == 0) { float m = red[0]; for (int w = 1; w < 16; w++) m = fmaxf(m, red[w]); red[0] = m; }
    __syncthreads();
    float mx = red[0];
    __syncthreads();
    float lsum = 0.f;
    for (int i = tid; i < SS; i += 512) { float e_ = __expf(v[i] - mx); v[i] = e_; lsum += e_; }
    #pragma unroll
    for (int o = 16; o > 0; o >>= 1) lsum += __shfl_down_sync(0xffffffffu, lsum, o);
    if ((tid & 31) == 0) red[tid>>5] = lsum;
    __syncthreads();
    if (tid == 0) { float s_ = 0.f; for (int w = 0; w < 16; w++) s_ += red[w]; red[0] = s_; }
    __syncthreads();
    float inv = 1.f / red[0];
    for (int i = tid; i < SS; i += 512) v[i] *= inv;
    for (int k = 2; k <= SS; k <<= 1)
        for (int j = k >> 1; j > 0; j >>= 1) {
            __syncthreads();
            for (int i = tid; i < SS; i += 512) {
                int p = i ^ j;
                if (p > i) {
                    bool dsc = ((i & k) == 0);
                    float vi = v[i], vp = v[p];
                    if (dsc ? (vi < vp) : (vi > vp)) {
                        v[i] = vp; v[p] = vi;
                        int tt = ix[i]; ix[i] = ix[p]; ix[p] = tt;
                    }
                }
            }
        }
    __syncthreads();
    for (int i = tid; i < KCAP; i += 512) {
        g_gate[(size_t)r*KCAP+i] = v[i];
        g_tok[(size_t)r*KCAP+i]  = ix[i];
    }
}

// ---------------- fused gate+up wmma GEMM (register-prefetch pipelined) -----
__global__ void __launch_bounds__(256) k_gateup(
    const float* __restrict__ A, const float* __restrict__ Wg,
    const float* __restrict__ Wu, float* __restrict__ Hout,
    const long long* __restrict__ labels, int gather, int wexp, int pmode)
{
    extern __shared__ __align__(16) char smem[];
    const int tid = threadIdx.x;
    const int y = blockIdx.y;
    const int n0 = blockIdx.x * 64;
    if (pmode == 1) { if (labels[y >> 3] != UNCOND_LABEL) return; }
    if (pmode == 2) { if (labels[y >> 4] == UNCOND_LABEL) return; }
    if (wexp) {
        size_t wo = (size_t)((y >> 1) & 7) * DD * IM;
        Wg += wo; Wu += wo;
    }
    int* arow = (int*)smem;
    if (tid < 128) {
        int r;
        if (gather) { int rowg = y * 128 + tid; r = (rowg >> 11) * SS + g_tok[rowg]; }
        else        r = y * 128 + tid;
        arow[tid] = r;
    }
    __syncthreads();

    const int lane = tid & 31, w = tid >> 5;
    const int wm = w & 1, wn = w >> 1;

    // per-thread staging coordinates (fixed across chunks)
    const int a_row = tid >> 1;                 // pairs: 2 f4 per thread per array? no:
    // A: 4 f4/thread: idx = i*256+tid -> row=idx>>3, f4=idx&7
    // B: 4 f4/thread: idx -> mat=idx>>9, k=(idx&511)>>4, f4=idx&15
    (void)a_row;

    wmma::fragment<wmma::accumulator, 16, 16, 16, float> accg[4], accu[4];
    #pragma unroll
    for (int mi = 0; mi < 4; mi++) { wmma::fill_fragment(accg[mi], 0.f); wmma::fill_fragment(accu[mi], 0.f); }

    const bf16* sA  = (const bf16*)(smem + 1024);
    const bf16* sBg = (const bf16*)(smem + 1024 + 20480);
    const bf16* sBu = (const bf16*)(smem + 1024 + 20480 + 9216);

    float4 pa[4], pb[4];
    // prefetch chunk 0
    #pragma unroll
    for (int i = 0; i < 4; i++) {
        int idx = i * 256 + tid;
        int row = idx >> 3, f4 = idx & 7;
        pa[i] = *(const float4*)(A + (size_t)arow[row] * DD + f4 * 4);
    }
    #pragma unroll
    for (int i = 0; i < 4; i++) {
        int idx = i * 256 + tid;
        int mat = idx >> 9, rem = idx & 511;
        int k = rem >> 4, f4 = rem & 15;
        pb[i] = *(const float4*)((mat ? Wu : Wg) + (size_t)k * IM + n0 + f4 * 4);
    }

    for (int k0 = 0; k0 < DD; k0 += 32) {
        __syncthreads();   // prior compute done before overwriting stage
        #pragma unroll
        for (int i = 0; i < 4; i++) {
            int idx = i * 256 + tid;
            int row = idx >> 3, f4 = idx & 7;
            uint2 hp, lp; split4(pa[i], hp, lp);
            *(uint2*)(smem + 1024 + row * 80 + f4 * 8)         = hp;
            *(uint2*)(smem + 1024 + 10240 + row * 80 + f4 * 8) = lp;
        }
        #pragma unroll
        for (int i = 0; i < 4; i++) {
            int idx = i * 256 + tid;
            int mat = idx >> 9, rem = idx & 511;
            int k = rem >> 4, f4 = rem & 15;
            uint2 hp, lp; split4(pb[i], hp, lp);
            char* bb = smem + 1024 + 20480 + mat * 9216 + k * 144 + f4 * 8;
            *(uint2*)bb          = hp;
            *(uint2*)(bb + 4608) = lp;
        }
        __syncthreads();
        if (k0 + 32 < DD) {  // issue next chunk's loads; latency hides under compute
            const int kn = k0 + 32;
            #pragma unroll
            for (int i = 0; i < 4; i++) {
                int idx = i * 256 + tid;
                int row = idx >> 3, f4 = idx & 7;
                pa[i] = *(const float4*)(A + (size_t)arow[row] * DD + kn + f4 * 4);
            }
            #pragma unroll
            for (int i = 0; i < 4; i++) {
                int idx = i * 256 + tid;
                int mat = idx >> 9, rem = idx & 511;
                int k = rem >> 4, f4 = rem & 15;
                pb[i] = *(const float4*)((mat ? Wu : Wg) + (size_t)(kn + k) * IM + n0 + f4 * 4);
            }
        }
        #pragma unroll
        for (int kk = 0; kk < 32; kk += 16) {
            wmma::fragment<wmma::matrix_b, 16, 16, 16, bf16, wmma::row_major> fgh, fgl, fuh, ful;
            wmma::load_matrix_sync(fgh, sBg + kk * 72 + wn * 16, 72);
            wmma::load_matrix_sync(fgl, sBg + 2304 + kk * 72 + wn * 16, 72);
            wmma::load_matrix_sync(fuh, sBu + kk * 72 + wn * 16, 72);
            wmma::load_matrix_sync(ful, sBu + 2304 + kk * 72 + wn * 16, 72);
            #pragma unroll
            for (int mi = 0; mi < 4; mi++) {
                wmma::fragment<wmma::matrix_a, 16, 16, 16, bf16, wmma::row_major> fah, fal;
                const bf16* ap = sA + (wm * 64 + mi * 16) * 40 + kk;
                wmma::load_matrix_sync(fah, ap, 40);
                wmma::load_matrix_sync(fal, ap + 5120, 40);
                wmma::mma_sync(accg[mi], fah, fgh, accg[mi]);
                wmma::mma_sync(accg[mi], fah, fgl, accg[mi]);
                wmma::mma_sync(accg[mi], fal, fgh, accg[mi]);
                wmma::mma_sync(accu[mi], fah, fuh, accu[mi]);
                wmma::mma_sync(accu[mi], fah, ful, accu[mi]);
                wmma::mma_sync(accu[mi], fal, fuh, accu[mi]);
            }
        }
    }
    __syncthreads();

    float* sg = (float*)(smem + 1024 + w * 2560);
    float* su = sg + 320;
    #pragma unroll
    for (int mi = 0; mi < 4; mi++) {
        wmma::store_matrix_sync(sg, accg[mi], 20, wmma::mem_row_major);
        wmma::store_matrix_sync(su, accu[mi], 20, wmma::mem_row_major);
        __syncwarp();
        int rb = y * 128 + wm * 64 + mi * 16;
        int cb = n0 + wn * 16;
        #pragma unroll
        for (int t = 0; t < 8; t++) {
            int idx = lane * 8 + t;
            int r16 = idx >> 4, c16 = idx & 15;
            float g = sg[r16 * 20 + c16];
            float u = su[r16 * 20 + c16];
            float h = g / (1.f + __expf(-g)) * u;
            g_H[(size_t)(rb + r16) * IM + cb + c16] = h;
        }
        __syncwarp();
    }
    (void)Hout;
}

// ---------------- down wmma GEMM (register-prefetch pipelined) --------------
__global__ void __launch_bounds__(256) k_down(
    const float* __restrict__ W, float* __restrict__ outp,
    const long long* __restrict__ labels, int wexp, int pmode, int emode)
{
    extern __shared__ __align__(16) char smem[];
    const int tid = threadIdx.x;
    const int y = blockIdx.y;
    const int n0 = blockIdx.x * 128;
    if (pmode == 1) { if (labels[y >> 3] != UNCOND_LABEL) return; }
    if (pmode == 2) { if (labels[y >> 4] == UNCOND_LABEL) return; }
    if (wexp) W += (size_t)((y >> 1) & 7) * IM * DD;

    const int lane = tid & 31, w = tid >> 5;
    const int wm = w & 1, wn = w >> 1;

    wmma::fragment<wmma::accumulator, 16, 16, 16, float> acc[4][2];
    #pragma unroll
    for (int mi = 0; mi < 4; mi++)
        #pragma unroll
        for (int nj = 0; nj < 2; nj++) wmma::fill_fragment(acc[mi][nj], 0.f);

    const bf16* sA = (const bf16*)(smem + 1024);
    const bf16* sB = (const bf16*)(smem + 1024 + 20480);

    float4 pa[4], pb[4];
    #pragma unroll
    for (int i = 0; i < 4; i++) {
        int idx = i * 256 + tid;
        int row = idx >> 3, f4 = idx & 7;
        pa[i] = *(const float4*)(g_H + (size_t)(y * 128 + row) * IM + f4 * 4);
    }
    #pragma unroll
    for (int i = 0; i < 4; i++) {
        int idx = i * 256 + tid;
        int k = idx >> 5, f4 = idx & 31;
        pb[i] = *(const float4*)(W + (size_t)k * DD + n0 + f4 * 4);
    }

    for (int k0 = 0; k0 < IM; k0 += 32) {
        __syncthreads();
        #pragma unroll
        for (int i = 0; i < 4; i++) {
            int idx = i * 256 + tid;
            int row = idx >> 3, f4 = idx & 7;
            uint2 hp, lp; split4(pa[i], hp, lp);
            *(uint2*)(smem + 1024 + row * 80 + f4 * 8)         = hp;
            *(uint2*)(smem + 1024 + 10240 + row * 80 + f4 * 8) = lp;
        }
        #pragma unroll
        for (int i = 0; i < 4; i++) {
            int idx = i * 256 + tid;
            int k = idx >> 5, f4 = idx & 31;
            uint2 hp, lp; split4(pb[i], hp, lp);
            char* bb = smem + 1024 + 20480 + k * 272 + f4 * 8;
            *(uint2*)bb          = hp;
            *(uint2*)(bb + 8704) = lp;
        }
        __syncthreads();
        if (k0 + 32 < IM) {
            const int kn = k0 + 32;
            #pragma unroll
            for (int i = 0; i < 4; i++) {
                int idx = i * 256 + tid;
                int row = idx >> 3, f4 = idx & 7;
                pa[i] = *(const float4*)(g_H + (size_t)(y * 128 + row) * IM + kn + f4 * 4);
            }
            #pragma unroll
            for (int i = 0; i < 4; i++) {
                int idx = i * 256 + tid;
                int k = idx >> 5, f4 = idx & 31;
                pb[i] = *(const float4*)(W + (size_t)(kn + k) * DD + n0 + f4 * 4);
            }
        }
        #pragma unroll
        for (int kk = 0; kk < 32; kk += 16) {
            wmma::fragment<wmma::matrix_b, 16, 16, 16, bf16, wmma::row_major> fbh[2], fbl[2];
            #pragma unroll
            for (int nj = 0; nj < 2; nj++) {
                const bf16* bp = sB + kk * 136 + wn * 32 + nj * 16;
                wmma::load_matrix_sync(fbh[nj], bp, 136);
                wmma::load_matrix_sync(fbl[nj], bp + 4352, 136);
            }
            #pragma unroll
            for (int mi = 0; mi < 4; mi++) {
                wmma::fragment<wmma::matrix_a, 16, 16, 16, bf16, wmma::row_major> fah, fal;
                const bf16* ap = sA + (wm * 64 + mi * 16) * 40 + kk;
                wmma::load_matrix_sync(fah, ap, 40);
                wmma::load_matrix_sync(fal, ap + 5120, 40);
                #pragma unroll
                for (int nj = 0; nj < 2; nj++) {
                    wmma::mma_sync(acc[mi][nj], fah, fbh[nj], acc[mi][nj]);
                    wmma::mma_sync(acc[mi][nj], fah, fbl[nj], acc[mi][nj]);
                    wmma::mma_sync(acc[mi][nj], fal, fbh[nj], acc[mi][nj]);
                }
            }
        }
    }
    __syncthreads();

    float* scr = (float*)(smem + 1024 + w * 1280);
    #pragma unroll
    for (int mi = 0; mi < 4; mi++) {
        #pragma unroll
        for (int nj = 0; nj < 2; nj++) {
            wmma::store_matrix_sync(scr, acc[mi][nj], 20, wmma::mem_row_major);
            __syncwarp();
            int rb = y * 128 + wm * 64 + mi * 16;
            int cb = n0 + wn * 32 + nj * 16;
            #pragma unroll
            for (int t = 0; t < 8; t++) {
                int idx = lane * 8 + t;
                int r16 = idx >> 4, c16 = idx & 15;
                float v = scr[r16 * 20 + c16];
                int r = rb + r16, c = cb + c16;
                if (emode == 0)      outp[(size_t)r * DD + c] = v;
                else if (emode == 1) outp[(size_t)r * DD + c] += v;
                else {
                    int tok = g_tok[r];
                    float wgt = g_gate[r];
                    int b = r >> 11;
                    atomicAdd(&outp[((size_t)b * SS + tok) * DD + c], wgt * v);
                }
            }
            __syncwarp();
        }
    }
}

// ---------------- launch ----------------------------------------------------
extern "C" void kernel_launch(void* const* d_in, const int* in_sizes, int n_in,
                              void* d_out, int out_size) {
    const float* hidden = (const float*)d_in[0];
    const long long* labels = (const long long*)d_in[1];
    const float* centers = (const float*)d_in[2];
    const float* Wg = (const float*)d_in[3];
    const float* Wu = (const float*)d_in[4];
    const float* Wd = (const float*)d_in[5];
    const float* uWg = (const float*)d_in[6];
    const float* uWu = (const float*)d_in[7];
    const float* uWd = (const float*)d_in[8];
    const float* sWg = (const float*)d_in[9];
    const float* sWu = (const float*)d_in[10];
    const float* sWd = (const float*)d_in[11];
    float* outp = (float*)d_out;

    // router
    k_norm_centers<<<EE, 256>>>(centers);
    k_router<<<BB * SS, 256>>>(hidden);
    k_softmax_topk<<<BB * EE, 512>>>();

    // shared expert
    k_gateup<<<dim3(IM/64, NTOK/128), 256, GU_SMEM>>>(hidden, sWg, sWu, g_H, labels, 0, 0, 0);
    k_down  <<<dim3(DD/128, NTOK/128), 256, DN_SMEM>>>(sWd, outp, labels, 0, 0, 0);

    // uncond expert (label==1000 batches), reuses g_H
    k_gateup<<<dim3(IM/64, NTOK/128), 256, GU_SMEM>>>(hidden, uWg, uWu, g_H, labels, 0, 0, 1);
    k_down  <<<dim3(DD/128, NTOK/128), 256, DN_SMEM>>>(uWd, outp, labels, 0, 1, 1);

    // routed experts (gathered A, per-expert weights, gated atomic scatter)
    k_gateup<<<dim3(IM/64, NROUT/128), 256, GU_SMEM>>>(hidden, Wg, Wu, g_H, labels, 1, 1, 2);
    k_down  <<<dim3(DD/128, NROUT/128), 256, DN_SMEM>>>(Wd, outp, labels, 1, 2, 2);
}

// round 13
// speedup vs baseline: 1.6818x; 1.6818x over previous
#include <cuda_runtime.h>
#include <cuda_bf16.h>
#include <mma.h>
#include <math.h>
#include <stdint.h>

using namespace nvcuda;

#define BB 16
#define SS 1024
#define DD 1024
#define EE 8
#define IM 2048
#define KCAP 256
#define UNCOND_LABEL 1000LL
#define NTOK (BB*SS)
#define NROUT (BB*EE*KCAP)

typedef __nv_bfloat16 bf16;

#define GU_SMEM (1024 + 38912)
#define DN_SMEM (1024 + 37888)

// ---------------- scratch (269MB — proven loadable) ----------------
__device__ float g_cn[EE*DD];
__device__ float g_cos[BB*EE*SS];
__device__ float g_gate[NROUT];
__device__ int   g_tok[NROUT];
__device__ float g_H[(size_t)NROUT * IM];   // fp32; dense phases use rows 0..16383

// ---------------- split helper ----------------
__device__ __forceinline__ void split4(float4 v, uint2& hp, uint2& lp) {
    float vv[4] = {v.x, v.y, v.z, v.w};
    __align__(8) bf16 h[4];
    __align__(8) bf16 l[4];
    #pragma unroll
    for (int j = 0; j < 4; j++) {
        h[j] = __float2bfloat16_rn(vv[j]);
        l[j] = __float2bfloat16_rn(vv[j] - __bfloat162float(h[j]));
    }
    hp = *(uint2*)h; lp = *(uint2*)l;
}

// ---------------- router (proven correct) ----------------
__global__ void k_norm_centers(const float* __restrict__ c) {
    int e = blockIdx.x, tid = threadIdx.x;
    float ss = 0.f;
    for (int j = tid; j < DD; j += 256) { float v = c[e*DD+j]; ss += v*v; }
    #pragma unroll
    for (int o = 16; o > 0; o >>= 1) ss += __shfl_down_sync(0xffffffffu, ss, o);
    __shared__ float red[8];
    if ((tid & 31) == 0) red[tid>>5] = ss;
    __syncthreads();
    if (tid == 0) { float t = 0.f; for (int w = 0; w < 8; w++) t += red[w]; red[0] = t; }
    __syncthreads();
    float inv = 1.f / fmaxf(sqrtf(red[0]), 1e-12f);
    for (int j = tid; j < DD; j += 256) g_cn[e*DD+j] = c[e*DD+j] * inv;
}

__global__ void k_router(const float* __restrict__ hidden) {
    int t = blockIdx.x, b = t >> 10, s = t & 1023, tid = threadIdx.x;
    const float* x = hidden + (size_t)t * DD;
    float acc[9];
    #pragma unroll
    for (int i = 0; i < 9; i++) acc[i] = 0.f;
    for (int j = tid; j < DD; j += 256) {
        float xv = x[j];
        acc[8] = fmaf(xv, xv, acc[8]);
        #pragma unroll
        for (int e = 0; e < EE; e++) acc[e] = fmaf(xv, g_cn[e*DD+j], acc[e]);
    }
    #pragma unroll
    for (int o = 16; o > 0; o >>= 1) {
        #pragma unroll
        for (int i = 0; i < 9; i++) acc[i] += __shfl_down_sync(0xffffffffu, acc[i], o);
    }
    __shared__ float sr[72];
    int lane = tid & 31, wd = tid >> 5;
    if (lane == 0) {
        #pragma unroll
        for (int i = 0; i < 9; i++) sr[i*8+wd] = acc[i];
    }
    __syncthreads();
    if (tid < EE) {
        float nrm = 0.f;
        for (int w = 0; w < 8; w++) nrm += sr[64+w];
        nrm = fmaxf(sqrtf(nrm), 1e-12f);
        float d = 0.f;
        for (int w = 0; w < 8; w++) d += sr[tid*8+w];
        g_cos[((size_t)b*EE+tid)*SS + s] = d / nrm;
    }
}

__global__ void k_softmax_topk() {
    int r = blockIdx.x, tid = threadIdx.x;
    __shared__ float v[SS]; __shared__ int ix[SS]; __shared__ float red[16];
    const float* row = g_cos + (size_t)r * SS;
    float lmax = -1e30f;
    for (int i = tid; i < SS; i += 512) { float t = row[i]; v[i] = t; ix[i] = i; lmax = fmaxf(lmax, t); }
    #pragma unroll
    for (int o = 16; o > 0; o >>= 1) lmax = fmaxf(lmax, __shfl_down_sync(0xffffffffu, lmax, o));
    if ((tid & 31) == 0) red[tid>>5] = lmax;
    __syncthreads();
    if (tid == 0) { float m = red[0]; for (int w = 1; w < 16; w++) m = fmaxf(m, red[w]); red[0] = m; }
    __syncthreads();
    float mx = red[0];
    __syncthreads();
    float lsum = 0.f;
    for (int i = tid; i < SS; i += 512) { float e_ = __expf(v[i] - mx); v[i] = e_; lsum += e_; }
    #pragma unroll
    for (int o = 16; o > 0; o >>= 1) lsum += __shfl_down_sync(0xffffffffu, lsum, o);
    if ((tid & 31) == 0) red[tid>>5] = lsum;
    __syncthreads();
    if (tid == 0) { float s_ = 0.f; for (int w = 0; w < 16; w++) s_ += red[w]; red[0] = s_; }
    __syncthreads();
    float inv = 1.f / red[0];
    for (int i = tid; i < SS; i += 512) v[i] *= inv;
    for (int k = 2; k <= SS; k <<= 1)
        for (int j = k >> 1; j > 0; j >>= 1) {
            __syncthreads();
            for (int i = tid; i < SS; i += 512) {
                int p = i ^ j;
                if (p > i) {
                    bool dsc = ((i & k) == 0);
                    float vi = v[i], vp = v[p];
                    if (dsc ? (vi < vp) : (vi > vp)) {
                        v[i] = vp; v[p] = vi;
                        int tt = ix[i]; ix[i] = ix[p]; ix[p] = tt;
                    }
                }
            }
        }
    __syncthreads();
    for (int i = tid; i < KCAP; i += 512) {
        g_gate[(size_t)r*KCAP+i] = v[i];
        g_tok[(size_t)r*KCAP+i]  = ix[i];
    }
}

// ---------------- fused gate+up wmma GEMM (2 CTAs/SM for overlap) -----------
__global__ void __launch_bounds__(256, 2) k_gateup(
    const float* __restrict__ A, const float* __restrict__ Wg,
    const float* __restrict__ Wu, float* __restrict__ Hout,
    const long long* __restrict__ labels, int gather, int wexp, int pmode)
{
    extern __shared__ __align__(16) char smem[];
    const int tid = threadIdx.x;
    const int y = blockIdx.y;
    const int n0 = blockIdx.x * 64;
    if (pmode == 1) { if (labels[y >> 3] != UNCOND_LABEL) return; }
    if (pmode == 2) { if (labels[y >> 4] == UNCOND_LABEL) return; }
    if (wexp) {
        size_t wo = (size_t)((y >> 1) & 7) * DD * IM;
        Wg += wo; Wu += wo;
    }
    int* arow = (int*)smem;
    if (tid < 128) {
        int r;
        if (gather) { int rowg = y * 128 + tid; r = (rowg >> 11) * SS + g_tok[rowg]; }
        else        r = y * 128 + tid;
        arow[tid] = r;
    }
    __syncthreads();

    const int lane = tid & 31, w = tid >> 5;
    const int wm = w & 1, wn = w >> 1;

    wmma::fragment<wmma::accumulator, 16, 16, 16, float> accg[4], accu[4];
    #pragma unroll
    for (int mi = 0; mi < 4; mi++) { wmma::fill_fragment(accg[mi], 0.f); wmma::fill_fragment(accu[mi], 0.f); }

    const bf16* sA  = (const bf16*)(smem + 1024);
    const bf16* sBg = (const bf16*)(smem + 1024 + 20480);
    const bf16* sBu = (const bf16*)(smem + 1024 + 20480 + 9216);

    for (int k0 = 0; k0 < DD; k0 += 32) {
        __syncthreads();
        #pragma unroll
        for (int i = 0; i < 4; i++) {
            int idx = i * 256 + tid;
            int row = idx >> 3, f4 = idx & 7;
            float4 v = *(const float4*)(A + (size_t)arow[row] * DD + k0 + f4 * 4);
            uint2 hp, lp; split4(v, hp, lp);
            *(uint2*)(smem + 1024 + row * 80 + f4 * 8)         = hp;
            *(uint2*)(smem + 1024 + 10240 + row * 80 + f4 * 8) = lp;
        }
        #pragma unroll
        for (int i = 0; i < 4; i++) {
            int idx = i * 256 + tid;
            int mat = idx >> 9, rem = idx & 511;
            int k = rem >> 4, f4 = rem & 15;
            float4 v = *(const float4*)((mat ? Wu : Wg) + (size_t)(k0 + k) * IM + n0 + f4 * 4);
            uint2 hp, lp; split4(v, hp, lp);
            char* bb = smem + 1024 + 20480 + mat * 9216 + k * 144 + f4 * 8;
            *(uint2*)bb          = hp;
            *(uint2*)(bb + 4608) = lp;
        }
        __syncthreads();
        #pragma unroll
        for (int kk = 0; kk < 32; kk += 16) {
            wmma::fragment<wmma::matrix_b, 16, 16, 16, bf16, wmma::row_major> fgh, fgl, fuh, ful;
            wmma::load_matrix_sync(fgh, sBg + kk * 72 + wn * 16, 72);
            wmma::load_matrix_sync(fgl, sBg + 2304 + kk * 72 + wn * 16, 72);
            wmma::load_matrix_sync(fuh, sBu + kk * 72 + wn * 16, 72);
            wmma::load_matrix_sync(ful, sBu + 2304 + kk * 72 + wn * 16, 72);
            #pragma unroll
            for (int mi = 0; mi < 4; mi++) {
                wmma::fragment<wmma::matrix_a, 16, 16, 16, bf16, wmma::row_major> fah, fal;
                const bf16* ap = sA + (wm * 64 + mi * 16) * 40 + kk;
                wmma::load_matrix_sync(fah, ap, 40);
                wmma::load_matrix_sync(fal, ap + 5120, 40);
                wmma::mma_sync(accg[mi], fah, fgh, accg[mi]);
                wmma::mma_sync(accg[mi], fah, fgl, accg[mi]);
                wmma::mma_sync(accg[mi], fal, fgh, accg[mi]);
                wmma::mma_sync(accu[mi], fah, fuh, accu[mi]);
                wmma::mma_sync(accu[mi], fah, ful, accu[mi]);
                wmma::mma_sync(accu[mi], fal, fuh, accu[mi]);
            }
        }
    }
    __syncthreads();

    float* sg = (float*)(smem + 1024 + w * 2560);
    float* su = sg + 320;
    #pragma unroll
    for (int mi = 0; mi < 4; mi++) {
        wmma::store_matrix_sync(sg, accg[mi], 20, wmma::mem_row_major);
        wmma::store_matrix_sync(su, accu[mi], 20, wmma::mem_row_major);
        __syncwarp();
        int rb = y * 128 + wm * 64 + mi * 16;
        int cb = n0 + wn * 16;
        #pragma unroll
        for (int t = 0; t < 8; t++) {
            int idx = lane * 8 + t;
            int r16 = idx >> 4, c16 = idx & 15;
            float g = sg[r16 * 20 + c16];
            float u = su[r16 * 20 + c16];
            float h = g / (1.f + __expf(-g)) * u;
            g_H[(size_t)(rb + r16) * IM + cb + c16] = h;
        }
        __syncwarp();
    }
    (void)Hout;
}

// ---------------- down wmma GEMM (2 CTAs/SM for overlap) --------------------
__global__ void __launch_bounds__(256, 2) k_down(
    const float* __restrict__ W, float* __restrict__ outp,
    const long long* __restrict__ labels, int wexp, int pmode, int emode)
{
    extern __shared__ __align__(16) char smem[];
    const int tid = threadIdx.x;
    const int y = blockIdx.y;
    const int n0 = blockIdx.x * 128;
    if (pmode == 1) { if (labels[y >> 3] != UNCOND_LABEL) return; }
    if (pmode == 2) { if (labels[y >> 4] == UNCOND_LABEL) return; }
    if (wexp) W += (size_t)((y >> 1) & 7) * IM * DD;

    const int lane = tid & 31, w = tid >> 5;
    const int wm = w & 1, wn = w >> 1;

    wmma::fragment<wmma::accumulator, 16, 16, 16, float> acc[4][2];
    #pragma unroll
    for (int mi = 0; mi < 4; mi++)
        #pragma unroll
        for (int nj = 0; nj < 2; nj++) wmma::fill_fragment(acc[mi][nj], 0.f);

    const bf16* sA = (const bf16*)(smem + 1024);
    const bf16* sB = (const bf16*)(smem + 1024 + 20480);

    for (int k0 = 0; k0 < IM; k0 += 32) {
        __syncthreads();
        #pragma unroll
        for (int i = 0; i < 4; i++) {
            int idx = i * 256 + tid;
            int row = idx >> 3, f4 = idx & 7;
            float4 v = *(const float4*)(g_H + (size_t)(y * 128 + row) * IM + k0 + f4 * 4);
            uint2 hp, lp; split4(v, hp, lp);
            *(uint2*)(smem + 1024 + row * 80 + f4 * 8)         = hp;
            *(uint2*)(smem + 1024 + 10240 + row * 80 + f4 * 8) = lp;
        }
        #pragma unroll
        for (int i = 0; i < 4; i++) {
            int idx = i * 256 + tid;
            int k = idx >> 5, f4 = idx & 31;
            float4 v = *(const float4*)(W + (size_t)(k0 + k) * DD + n0 + f4 * 4);
            uint2 hp, lp; split4(v, hp, lp);
            char* bb = smem + 1024 + 20480 + k * 272 + f4 * 8;
            *(uint2*)bb          = hp;
            *(uint2*)(bb + 8704) = lp;
        }
        __syncthreads();
        #pragma unroll
        for (int kk = 0; kk < 32; kk += 16) {
            wmma::fragment<wmma::matrix_b, 16, 16, 16, bf16, wmma::row_major> fbh[2], fbl[2];
            #pragma unroll
            for (int nj = 0; nj < 2; nj++) {
                const bf16* bp = sB + kk * 136 + wn * 32 + nj * 16;
                wmma::load_matrix_sync(fbh[nj], bp, 136);
                wmma::load_matrix_sync(fbl[nj], bp + 4352, 136);
            }
            #pragma unroll
            for (int mi = 0; mi < 4; mi++) {
                wmma::fragment<wmma::matrix_a, 16, 16, 16, bf16, wmma::row_major> fah, fal;
                const bf16* ap = sA + (wm * 64 + mi * 16) * 40 + kk;
                wmma::load_matrix_sync(fah, ap, 40);
                wmma::load_matrix_sync(fal, ap + 5120, 40);
                #pragma unroll
                for (int nj = 0; nj < 2; nj++) {
                    wmma::mma_sync(acc[mi][nj], fah, fbh[nj], acc[mi][nj]);
                    wmma::mma_sync(acc[mi][nj], fah, fbl[nj], acc[mi][nj]);
                    wmma::mma_sync(acc[mi][nj], fal, fbh[nj], acc[mi][nj]);
                }
            }
        }
    }
    __syncthreads();

    float* scr = (float*)(smem + 1024 + w * 1280);
    #pragma unroll
    for (int mi = 0; mi < 4; mi++) {
        #pragma unroll
        for (int nj = 0; nj < 2; nj++) {
            wmma::store_matrix_sync(scr, acc[mi][nj], 20, wmma::mem_row_major);
            __syncwarp();
            int rb = y * 128 + wm * 64 + mi * 16;
            int cb = n0 + wn * 32 + nj * 16;
            #pragma unroll
            for (int t = 0; t < 8; t++) {
                int idx = lane * 8 + t;
                int r16 = idx >> 4, c16 = idx & 15;
                float v = scr[r16 * 20 + c16];
                int r = rb + r16, c = cb + c16;
                if (emode == 0)      outp[(size_t)r * DD + c] = v;
                else if (emode == 1) outp[(size_t)r * DD + c] += v;
                else {
                    int tok = g_tok[r];
                    float wgt = g_gate[r];
                    int b = r >> 11;
                    atomicAdd(&outp[((size_t)b * SS + tok) * DD + c], wgt * v);
                }
            }
            __syncwarp();
        }
    }
}

// ---------------- launch ----------------------------------------------------
extern "C" void kernel_launch(void* const* d_in, const int* in_sizes, int n_in,
                              void* d_out, int out_size) {
    const float* hidden = (const float*)d_in[0];
    const long long* labels = (const long long*)d_in[1];
    const float* centers = (const float*)d_in[2];
    const float* Wg = (const float*)d_in[3];
    const float* Wu = (const float*)d_in[4];
    const float* Wd = (const float*)d_in[5];
    const float* uWg = (const float*)d_in[6];
    const float* uWu = (const float*)d_in[7];
    const float* uWd = (const float*)d_in[8];
    const float* sWg = (const float*)d_in[9];
    const float* sWu = (const float*)d_in[10];
    const float* sWd = (const float*)d_in[11];
    float* outp = (float*)d_out;

    // router
    k_norm_centers<<<EE, 256>>>(centers);
    k_router<<<BB * SS, 256>>>(hidden);
    k_softmax_topk<<<BB * EE, 512>>>();

    // shared expert (launches 4,5)
    k_gateup<<<dim3(IM/64, NTOK/128), 256, GU_SMEM>>>(hidden, sWg, sWu, g_H, labels, 0, 0, 0);
    k_down  <<<dim3(DD/128, NTOK/128), 256, DN_SMEM>>>(sWd, outp, labels, 0, 0, 0);

    // routed experts (launch 6 = heavy routed gateup → ncu -s 5 profiles it)
    k_gateup<<<dim3(IM/64, NROUT/128), 256, GU_SMEM>>>(hidden, Wg, Wu, g_H, labels, 1, 1, 2);
    k_down  <<<dim3(DD/128, NROUT/128), 256, DN_SMEM>>>(Wd, outp, labels, 1, 2, 2);

    // uncond expert (reuses g_H rows 0..16383 after routed down consumed them)
    k_gateup<<<dim3(IM/64, NTOK/128), 256, GU_SMEM>>>(hidden, uWg, uWu, g_H, labels, 0, 0, 1);
    k_down  <<<dim3(DD/128, NTOK/128), 256, DN_SMEM>>>(uWd, outp, labels, 0, 1, 1);
}

// round 16
// speedup vs baseline: 2.0028x; 1.1909x over previous
#include <cuda_runtime.h>
#include <cuda_bf16.h>
#include <mma.h>
#include <math.h>
#include <stdint.h>

using namespace nvcuda;

#define BB 16
#define SS 1024
#define DD 1024
#define EE 8
#define IM 2048
#define KCAP 256
#define UNCOND_LABEL 1000LL
#define NTOK (BB*SS)
#define NROUT (BB*EE*KCAP)

typedef __nv_bfloat16 bf16;

// layout: [0,1024) arow | [1024, +32768) fp32 stage S | bf16 buf Bb
#define GU_SMEM (1024 + 32768 + 38912)
#define DN_SMEM (1024 + 32768 + 37888)

// ---------------- scratch (269MB — proven loadable) ----------------
__device__ float g_cn[EE*DD];
__device__ float g_cos[BB*EE*SS];
__device__ float g_gate[NROUT];
__device__ int   g_tok[NROUT];
__device__ float g_H[(size_t)NROUT * IM];   // fp32; dense phases use rows 0..16383

// ---------------- helpers ----------------
__device__ __forceinline__ uint32_t smem_u32(const void* p) {
    uint32_t a;
    asm("{ .reg .u64 t; cvta.to.shared.u64 t, %1; cvt.u32.u64 %0, t; }" : "=r"(a) : "l"(p));
    return a;
}
#define CP16(s, g)  asm volatile("cp.async.cg.shared.global [%0], [%1], 16;" :: "r"(s), "l"(g))
#define CP_COMMIT() asm volatile("cp.async.commit_group;" ::: "memory")
#define CP_WAIT0()  asm volatile("cp.async.wait_group 0;" ::: "memory")

__device__ __forceinline__ void split4(float4 v, uint2& hp, uint2& lp) {
    float vv[4] = {v.x, v.y, v.z, v.w};
    __align__(8) bf16 h[4];
    __align__(8) bf16 l[4];
    #pragma unroll
    for (int j = 0; j < 4; j++) {
        h[j] = __float2bfloat16_rn(vv[j]);
        l[j] = __float2bfloat16_rn(vv[j] - __bfloat162float(h[j]));
    }
    hp = *(uint2*)h; lp = *(uint2*)l;
}

// ---------------- router (proven correct) ----------------
__global__ void k_norm_centers(const float* __restrict__ c) {
    int e = blockIdx.x, tid = threadIdx.x;
    float ss = 0.f;
    for (int j = tid; j < DD; j += 256) { float v = c[e*DD+j]; ss += v*v; }
    #pragma unroll
    for (int o = 16; o > 0; o >>= 1) ss += __shfl_down_sync(0xffffffffu, ss, o);
    __shared__ float red[8];
    if ((tid & 31) == 0) red[tid>>5] = ss;
    __syncthreads();
    if (tid == 0) { float t = 0.f; for (int w = 0; w < 8; w++) t += red[w]; red[0] = t; }
    __syncthreads();
    float inv = 1.f / fmaxf(sqrtf(red[0]), 1e-12f);
    for (int j = tid; j < DD; j += 256) g_cn[e*DD+j] = c[e*DD+j] * inv;
}

__global__ void k_router(const float* __restrict__ hidden) {
    int t = blockIdx.x, b = t >> 10, s = t & 1023, tid = threadIdx.x;
    const float* x = hidden + (size_t)t * DD;
    float acc[9];
    #pragma unroll
    for (int i = 0; i < 9; i++) acc[i] = 0.f;
    for (int j = tid; j < DD; j += 256) {
        float xv = x[j];
        acc[8] = fmaf(xv, xv, acc[8]);
        #pragma unroll
        for (int e = 0; e < EE; e++) acc[e] = fmaf(xv, g_cn[e*DD+j], acc[e]);
    }
    #pragma unroll
    for (int o = 16; o > 0; o >>= 1) {
        #pragma unroll
        for (int i = 0; i < 9; i++) acc[i] += __shfl_down_sync(0xffffffffu, acc[i], o);
    }
    __shared__ float sr[72];
    int lane = tid & 31, wd = tid >> 5;
    if (lane == 0) {
        #pragma unroll
        for (int i = 0; i < 9; i++) sr[i*8+wd] = acc[i];
    }
    __syncthreads();
    if (tid < EE) {
        float nrm = 0.f;
        for (int w = 0; w < 8; w++) nrm += sr[64+w];
        nrm = fmaxf(sqrtf(nrm), 1e-12f);
        float d = 0.f;
        for (int w = 0; w < 8; w++) d += sr[tid*8+w];
        g_cos[((size_t)b*EE+tid)*SS + s] = d / nrm;
    }
}

__global__ void k_softmax_topk() {
    int r = blockIdx.x, tid = threadIdx.x;
    __shared__ float v[SS]; __shared__ int ix[SS]; __shared__ float red[16];
    const float* row = g_cos + (size_t)r * SS;
    float lmax = -1e30f;
    for (int i = tid; i < SS; i += 512) { float t = row[i]; v[i] = t; ix[i] = i; lmax = fmaxf(lmax, t); }
    #pragma unroll
    for (int o = 16; o > 0; o >>= 1) lmax = fmaxf(lmax, __shfl_down_sync(0xffffffffu, lmax, o));
    if ((tid & 31) == 0) red[tid>>5] = lmax;
    __syncthreads();
    if (tid == 0) { float m = red[0]; for (int w = 1; w < 16; w++) m = fmaxf(m, red[w]); red[0] = m; }
    __syncthreads();
    float mx = red[0];
    __syncthreads();
    float lsum = 0.f;
    for (int i = tid; i < SS; i += 512) { float e_ = __expf(v[i] - mx); v[i] = e_; lsum += e_; }
    #pragma unroll
    for (int o = 16; o > 0; o >>= 1) lsum += __shfl_down_sync(0xffffffffu, lsum, o);
    if ((tid & 31) == 0) red[tid>>5] = lsum;
    __syncthreads();
    if (tid == 0) { float s_ = 0.f; for (int w = 0; w < 16; w++) s_ += red[w]; red[0] = s_; }
    __syncthreads();
    float inv = 1.f / red[0];
    for (int i = tid; i < SS; i += 512) v[i] *= inv;
    for (int k = 2; k <= SS; k <<= 1)
        for (int j = k >> 1; j > 0; j >>= 1) {
            __syncthreads();
            for (int i = tid; i < SS; i += 512) {
                int p = i ^ j;
                if (p > i) {
                    bool dsc = ((i & k) == 0);
                    float vi = v[i], vp = v[p];
                    if (dsc ? (vi < vp) : (vi > vp)) {
                        v[i] = vp; v[p] = vi;
                        int tt = ix[i]; ix[i] = ix[p]; ix[p] = tt;
                    }
                }
            }
        }
    __syncthreads();
    for (int i = tid; i < KCAP; i += 512) {
        g_gate[(size_t)r*KCAP+i] = v[i];
        g_tok[(size_t)r*KCAP+i]  = ix[i];
    }
}

// ---------------- fused gate+up wmma GEMM (cp.async pipelined, 2 CTA/SM) ----
__global__ void __launch_bounds__(256, 2) k_gateup(
    const float* __restrict__ A, const float* __restrict__ Wg,
    const float* __restrict__ Wu, float* __restrict__ Hout,
    const long long* __restrict__ labels, int gather, int wexp, int pmode)
{
    extern __shared__ __align__(16) char smem[];
    const int tid = threadIdx.x;
    const int y = blockIdx.y;
    const int n0 = blockIdx.x * 64;
    if (pmode == 1) { if (labels[y >> 3] != UNCOND_LABEL) return; }
    if (pmode == 2) { if (labels[y >> 4] == UNCOND_LABEL) return; }
    if (wexp) {
        size_t wo = (size_t)((y >> 1) & 7) * DD * IM;
        Wg += wo; Wu += wo;
    }
    int* arow = (int*)smem;
    if (tid < 128) {
        int r;
        if (gather) { int rowg = y * 128 + tid; r = (rowg >> 11) * SS + g_tok[rowg]; }
        else        r = y * 128 + tid;
        arow[tid] = r;
    }
    __syncthreads();

    const int lane = tid & 31, w = tid >> 5;
    const int wm = w & 1, wn = w >> 1;

    wmma::fragment<wmma::accumulator, 16, 16, 16, float> accg[4], accu[4];
    #pragma unroll
    for (int mi = 0; mi < 4; mi++) { wmma::fill_fragment(accg[mi], 0.f); wmma::fill_fragment(accu[mi], 0.f); }

    char* S  = smem + 1024;                 // fp32 stage: A 16KB @0, B 16KB @16384
    char* Bb = smem + 1024 + 32768;         // bf16 buffers
    const uint32_t sS = smem_u32(S);
    const bf16* sA  = (const bf16*)Bb;
    const bf16* sBg = (const bf16*)(Bb + 20480);
    const bf16* sBu = (const bf16*)(Bb + 20480 + 9216);

    // issue chunk 0
    #pragma unroll
    for (int i = 0; i < 4; i++) {
        int idx = i * 256 + tid;
        int row = idx >> 3, f4 = idx & 7;
        CP16(sS + idx * 16, A + (size_t)arow[row] * DD + f4 * 4);
    }
    #pragma unroll
    for (int i = 0; i < 4; i++) {
        int idx = i * 256 + tid;
        int mat = idx >> 9, rem = idx & 511;
        int k = rem >> 4, f4 = rem & 15;
        CP16(sS + 16384 + idx * 16, (mat ? Wu : Wg) + (size_t)k * IM + n0 + f4 * 4);
    }
    CP_COMMIT();

    for (int it = 0; it < DD / 32; ++it) {
        CP_WAIT0();
        __syncthreads();    // prev compute done (Bb free) + stage visible
        // split S -> Bb (each thread reads exactly the bytes it staged)
        #pragma unroll
        for (int i = 0; i < 4; i++) {
            int idx = i * 256 + tid;
            int row = idx >> 3, f4 = idx & 7;
            float4 v = *(const float4*)(S + idx * 16);
            uint2 hp, lp; split4(v, hp, lp);
            *(uint2*)(Bb + row * 80 + f4 * 8)         = hp;
            *(uint2*)(Bb + 10240 + row * 80 + f4 * 8) = lp;
        }
        #pragma unroll
        for (int i = 0; i < 4; i++) {
            int idx = i * 256 + tid;
            int mat = idx >> 9, rem = idx & 511;
            int k = rem >> 4, f4 = rem & 15;
            float4 v = *(const float4*)(S + 16384 + idx * 16);
            uint2 hp, lp; split4(v, hp, lp);
            char* bb = Bb + 20480 + mat * 9216 + k * 144 + f4 * 8;
            *(uint2*)bb          = hp;
            *(uint2*)(bb + 4608) = lp;
        }
        // prefetch next chunk into S (overlaps compute below)
        if (it + 1 < DD / 32) {
            const int kn = (it + 1) * 32;
            #pragma unroll
            for (int i = 0; i < 4; i++) {
                int idx = i * 256 + tid;
                int row = idx >> 3, f4 = idx & 7;
                CP16(sS + idx * 16, A + (size_t)arow[row] * DD + kn + f4 * 4);
            }
            #pragma unroll
            for (int i = 0; i < 4; i++) {
                int idx = i * 256 + tid;
                int mat = idx >> 9, rem = idx & 511;
                int k = rem >> 4, f4 = rem & 15;
                CP16(sS + 16384 + idx * 16, (mat ? Wu : Wg) + (size_t)(kn + k) * IM + n0 + f4 * 4);
            }
            CP_COMMIT();
        }
        __syncthreads();    // split visible to all warps
        #pragma unroll
        for (int kk = 0; kk < 32; kk += 16) {
            wmma::fragment<wmma::matrix_b, 16, 16, 16, bf16, wmma::row_major> fgh, fgl, fuh, ful;
            wmma::load_matrix_sync(fgh, sBg + kk * 72 + wn * 16, 72);
            wmma::load_matrix_sync(fgl, sBg + 2304 + kk * 72 + wn * 16, 72);
            wmma::load_matrix_sync(fuh, sBu + kk * 72 + wn * 16, 72);
            wmma::load_matrix_sync(ful, sBu + 2304 + kk * 72 + wn * 16, 72);
            #pragma unroll
            for (int mi = 0; mi < 4; mi++) {
                wmma::fragment<wmma::matrix_a, 16, 16, 16, bf16, wmma::row_major> fah, fal;
                const bf16* ap = sA + (wm * 64 + mi * 16) * 40 + kk;
                wmma::load_matrix_sync(fah, ap, 40);
                wmma::load_matrix_sync(fal, ap + 5120, 40);
                wmma::mma_sync(accg[mi], fah, fgh, accg[mi]);
                wmma::mma_sync(accg[mi], fah, fgl, accg[mi]);
                wmma::mma_sync(accg[mi], fal, fgh, accg[mi]);
                wmma::mma_sync(accu[mi], fah, fuh, accu[mi]);
                wmma::mma_sync(accu[mi], fah, ful, accu[mi]);
                wmma::mma_sync(accu[mi], fal, fuh, accu[mi]);
            }
        }
    }
    __syncthreads();

    float* sg = (float*)(S + w * 2560);     // stage region reused as scratch
    float* su = sg + 320;
    #pragma unroll
    for (int mi = 0; mi < 4; mi++) {
        wmma::store_matrix_sync(sg, accg[mi], 20, wmma::mem_row_major);
        wmma::store_matrix_sync(su, accu[mi], 20, wmma::mem_row_major);
        __syncwarp();
        int rb = y * 128 + wm * 64 + mi * 16;
        int cb = n0 + wn * 16;
        #pragma unroll
        for (int t = 0; t < 8; t++) {
            int idx = lane * 8 + t;
            int r16 = idx >> 4, c16 = idx & 15;
            float g = sg[r16 * 20 + c16];
            float u = su[r16 * 20 + c16];
            float h = g / (1.f + __expf(-g)) * u;
            g_H[(size_t)(rb + r16) * IM + cb + c16] = h;
        }
        __syncwarp();
    }
    (void)Hout;
}

// ---------------- down wmma GEMM (cp.async pipelined, 2 CTA/SM) -------------
__global__ void __launch_bounds__(256, 2) k_down(
    const float* __restrict__ W, float* __restrict__ outp,
    const long long* __restrict__ labels, int wexp, int pmode, int emode)
{
    extern __shared__ __align__(16) char smem[];
    const int tid = threadIdx.x;
    const int y = blockIdx.y;
    const int n0 = blockIdx.x * 128;
    if (pmode == 1) { if (labels[y >> 3] != UNCOND_LABEL) return; }
    if (pmode == 2) { if (labels[y >> 4] == UNCOND_LABEL) return; }
    if (wexp) W += (size_t)((y >> 1) & 7) * IM * DD;

    const int lane = tid & 31, w = tid >> 5;
    const int wm = w & 1, wn = w >> 1;

    wmma::fragment<wmma::accumulator, 16, 16, 16, float> acc[4][2];
    #pragma unroll
    for (int mi = 0; mi < 4; mi++)
        #pragma unroll
        for (int nj = 0; nj < 2; nj++) wmma::fill_fragment(acc[mi][nj], 0.f);

    char* S  = smem + 1024;
    char* Bb = smem + 1024 + 32768;
    const uint32_t sS = smem_u32(S);
    const bf16* sA = (const bf16*)Bb;
    const bf16* sB = (const bf16*)(Bb + 20480);

    #pragma unroll
    for (int i = 0; i < 4; i++) {
        int idx = i * 256 + tid;
        int row = idx >> 3, f4 = idx & 7;
        CP16(sS + idx * 16, g_H + (size_t)(y * 128 + row) * IM + f4 * 4);
    }
    #pragma unroll
    for (int i = 0; i < 4; i++) {
        int idx = i * 256 + tid;
        int k = idx >> 5, f4 = idx & 31;
        CP16(sS + 16384 + idx * 16, W + (size_t)k * DD + n0 + f4 * 4);
    }
    CP_COMMIT();

    for (int it = 0; it < IM / 32; ++it) {
        CP_WAIT0();
        __syncthreads();
        #pragma unroll
        for (int i = 0; i < 4; i++) {
            int idx = i * 256 + tid;
            int row = idx >> 3, f4 = idx & 7;
            float4 v = *(const float4*)(S + idx * 16);
            uint2 hp, lp; split4(v, hp, lp);
            *(uint2*)(Bb + row * 80 + f4 * 8)         = hp;
            *(uint2*)(Bb + 10240 + row * 80 + f4 * 8) = lp;
        }
        #pragma unroll
        for (int i = 0; i < 4; i++) {
            int idx = i * 256 + tid;
            int k = idx >> 5, f4 = idx & 31;
            float4 v = *(const float4*)(S + 16384 + idx * 16);
            uint2 hp, lp; split4(v, hp, lp);
            char* bb = Bb + 20480 + k * 272 + f4 * 8;
            *(uint2*)bb          = hp;
            *(uint2*)(bb + 8704) = lp;
        }
        if (it + 1 < IM / 32) {
            const int kn = (it + 1) * 32;
            #pragma unroll
            for (int i = 0; i < 4; i++) {
                int idx = i * 256 + tid;
                int row = idx >> 3, f4 = idx & 7;
                CP16(sS + idx * 16, g_H + (size_t)(y * 128 + row) * IM + kn + f4 * 4);
            }
            #pragma unroll
            for (int i = 0; i < 4; i++) {
                int idx = i * 256 + tid;
                int k = idx >> 5, f4 = idx & 31;
                CP16(sS + 16384 + idx * 16, W + (size_t)(kn + k) * DD + n0 + f4 * 4);
            }
            CP_COMMIT();
        }
        __syncthreads();
        #pragma unroll
        for (int kk = 0; kk < 32; kk += 16) {
            wmma::fragment<wmma::matrix_b, 16, 16, 16, bf16, wmma::row_major> fbh[2], fbl[2];
            #pragma unroll
            for (int nj = 0; nj < 2; nj++) {
                const bf16* bp = sB + kk * 136 + wn * 32 + nj * 16;
                wmma::load_matrix_sync(fbh[nj], bp, 136);
                wmma::load_matrix_sync(fbl[nj], bp + 4352, 136);
            }
            #pragma unroll
            for (int mi = 0; mi < 4; mi++) {
                wmma::fragment<wmma::matrix_a, 16, 16, 16, bf16, wmma::row_major> fah, fal;
                const bf16* ap = sA + (wm * 64 + mi * 16) * 40 + kk;
                wmma::load_matrix_sync(fah, ap, 40);
                wmma::load_matrix_sync(fal, ap + 5120, 40);
                #pragma unroll
                for (int nj = 0; nj < 2; nj++) {
                    wmma::mma_sync(acc[mi][nj], fah, fbh[nj], acc[mi][nj]);
                    wmma::mma_sync(acc[mi][nj], fah, fbl[nj], acc[mi][nj]);
                    wmma::mma_sync(acc[mi][nj], fal, fbh[nj], acc[mi][nj]);
                }
            }
        }
    }
    __syncthreads();

    float* scr = (float*)(S + w * 1280);
    #pragma unroll
    for (int mi = 0; mi < 4; mi++) {
        #pragma unroll
        for (int nj = 0; nj < 2; nj++) {
            wmma::store_matrix_sync(scr, acc[mi][nj], 20, wmma::mem_row_major);
            __syncwarp();
            int rb = y * 128 + wm * 64 + mi * 16;
            int cb = n0 + wn * 32 + nj * 16;
            #pragma unroll
            for (int t = 0; t < 8; t++) {
                int idx = lane * 8 + t;
                int r16 = idx >> 4, c16 = idx & 15;
                float v = scr[r16 * 20 + c16];
                int r = rb + r16, c = cb + c16;
                if (emode == 0)      outp[(size_t)r * DD + c] = v;
                else if (emode == 1) outp[(size_t)r * DD + c] += v;
                else {
                    int tok = g_tok[r];
                    float wgt = g_gate[r];
                    int b = r >> 11;
                    atomicAdd(&outp[((size_t)b * SS + tok) * DD + c], wgt * v);
                }
            }
            __syncwarp();
        }
    }
}

// ---------------- launch ----------------------------------------------------
extern "C" void kernel_launch(void* const* d_in, const int* in_sizes, int n_in,
                              void* d_out, int out_size) {
    const float* hidden = (const float*)d_in[0];
    const long long* labels = (const long long*)d_in[1];
    const float* centers = (const float*)d_in[2];
    const float* Wg = (const float*)d_in[3];
    const float* Wu = (const float*)d_in[4];
    const float* Wd = (const float*)d_in[5];
    const float* uWg = (const float*)d_in[6];
    const float* uWu = (const float*)d_in[7];
    const float* uWd = (const float*)d_in[8];
    const float* sWg = (const float*)d_in[9];
    const float* sWu = (const float*)d_in[10];
    const float* sWd = (const float*)d_in[11];
    float* outp = (float*)d_out;

    cudaFuncSetAttribute(k_gateup, cudaFuncAttributeMaxDynamicSharedMemorySize, GU_SMEM);
    cudaFuncSetAttribute(k_down,   cudaFuncAttributeMaxDynamicSharedMemorySize, DN_SMEM);

    // router
    k_norm_centers<<<EE, 256>>>(centers);
    k_router<<<BB * SS, 256>>>(hidden);
    k_softmax_topk<<<BB * EE, 512>>>();

    // shared expert
    k_gateup<<<dim3(IM/64, NTOK/128), 256, GU_SMEM>>>(hidden, sWg, sWu, g_H, labels, 0, 0, 0);
    k_down  <<<dim3(DD/128, NTOK/128), 256, DN_SMEM>>>(sWd, outp, labels, 0, 0, 0);

    // routed experts (gathered A, per-expert weights, gated atomic scatter)
    k_gateup<<<dim3(IM/64, NROUT/128), 256, GU_SMEM>>>(hidden, Wg, Wu, g_H, labels, 1, 1, 2);
    k_down  <<<dim3(DD/128, NROUT/128), 256, DN_SMEM>>>(Wd, outp, labels, 1, 2, 2);

    // uncond expert (reuses g_H rows 0..16383 after routed down consumed them)
    k_gateup<<<dim3(IM/64, NTOK/128), 256, GU_SMEM>>>(hidden, uWg, uWu, g_H, labels, 0, 0, 1);
    k_down  <<<dim3(DD/128, NTOK/128), 256, DN_SMEM>>>(uWd, outp, labels, 0, 1, 1);
}